// round 4
// baseline (speedup 1.0000x reference)
#include <cuda_runtime.h>
#include <math_constants.h>

// Problem constants: B=4, S=2048, D=512
#define BATCH 4
#define SEQ   2048
#define DIM   512

// Scratch (device globals — allocation-free per harness rules)
__device__ float g_qkv[BATCH * SEQ * 3 * DIM];     // 48 MiB: [b, s, 3D] (q|k|v)
__device__ float g_scores[BATCH * SEQ * SEQ];      // 64 MiB: [b, q, k]
__device__ float g_attn[BATCH * SEQ * DIM];        // 16 MiB: [b, s, D]

// ---------------------------------------------------------------------------
// Double-buffered SGEMM, 128x128 block tile, BK=8, 256 threads, 8x8/thread.
// Fragment loads from smem forced to LDS.128 (float4; row pitches 528B/512B
// are 16B multiples so every k-row stays 16B-aligned).
// ---------------------------------------------------------------------------
#define BM 128
#define BN 128
#define BK 8
#define TM 8
#define TN 8

__device__ __forceinline__ void mm_step(
    const float* __restrict__ AsRow, const float* __restrict__ BsRow,
    float acc[TM][TN])
{
    // AsRow/BsRow point at As[k][threadRow*TM] / Bs[k][threadCol*TN] (32B aligned)
    const float4 m0 = *reinterpret_cast<const float4*>(AsRow);
    const float4 m1 = *reinterpret_cast<const float4*>(AsRow + 4);
    const float4 n0 = *reinterpret_cast<const float4*>(BsRow);
    const float4 n1 = *reinterpret_cast<const float4*>(BsRow + 4);
    const float regM[TM] = {m0.x, m0.y, m0.z, m0.w, m1.x, m1.y, m1.z, m1.w};
    const float regN[TN] = {n0.x, n0.y, n0.z, n0.w, n1.x, n1.y, n1.z, n1.w};
    #pragma unroll
    for (int i = 0; i < TM; i++)
        #pragma unroll
        for (int j = 0; j < TN; j++)
            acc[i][j] += regM[i] * regN[j];
}

// ---------------------------------------------------------------------------
// NT: C[m,n] = s(n) * (sum_k A[m,k] * B[n,k] + bias[n])
// where s(n) = alpha * (scale_q_cols && n < DIM ? 512^-0.5 : 1).
// A: [M,K] row-major (lda), B: [N,K] row-major (ldb), C: [M,N] (ldc)
// ---------------------------------------------------------------------------
__global__ __launch_bounds__(256, 2)
void sgemm_nt(int M, int N, int K,
              const float* __restrict__ A, int lda, long strideA,
              const float* __restrict__ B, int ldb, long strideB,
              float* __restrict__ C, int ldc, long strideC,
              const float* __restrict__ bias, float alpha, int scale_q_cols)
{
    const int bz = blockIdx.z;
    A += bz * strideA;
    B += bz * strideB;
    C += bz * strideC;

    const int cCol = blockIdx.x;  // N tile
    const int cRow = blockIdx.y;  // M tile

    __shared__ __align__(16) float As[2][BK][BM + 4];  // pitch 528B (16B mult)
    __shared__ __align__(16) float Bs[2][BK][BN + 4];

    const int tid = threadIdx.x;
    const int threadCol = tid % (BN / TN);  // 0..15
    const int threadRow = tid / (BN / TN);  // 0..15

    const int aRow = tid >> 1;          // 0..127
    const int aCol = (tid & 1) * 4;     // 0 or 4
    const int bRow = tid >> 1;
    const int bCol = (tid & 1) * 4;

    const float* Aptr = A + (long)(cRow * BM + aRow) * lda + aCol;
    const float* Bptr = B + (long)(cCol * BN + bRow) * ldb + bCol;

    float acc[TM][TN];
    #pragma unroll
    for (int i = 0; i < TM; i++)
        #pragma unroll
        for (int j = 0; j < TN; j++) acc[i][j] = 0.0f;

    // prologue: tile 0 -> buffer 0
    float4 a4 = *reinterpret_cast<const float4*>(Aptr);
    float4 b4 = *reinterpret_cast<const float4*>(Bptr);
    As[0][aCol + 0][aRow] = a4.x;
    As[0][aCol + 1][aRow] = a4.y;
    As[0][aCol + 2][aRow] = a4.z;
    As[0][aCol + 3][aRow] = a4.w;
    Bs[0][bCol + 0][bRow] = b4.x;
    Bs[0][bCol + 1][bRow] = b4.y;
    Bs[0][bCol + 2][bRow] = b4.z;
    Bs[0][bCol + 3][bRow] = b4.w;
    __syncthreads();

    int buf = 0;
    for (int k0 = BK; k0 < K; k0 += BK) {
        Aptr += BK;
        Bptr += BK;
        a4 = *reinterpret_cast<const float4*>(Aptr);   // prefetch next tile
        b4 = *reinterpret_cast<const float4*>(Bptr);

        #pragma unroll
        for (int k = 0; k < BK; k++)
            mm_step(&As[buf][k][threadRow * TM], &Bs[buf][k][threadCol * TN], acc);

        const int nb = buf ^ 1;
        As[nb][aCol + 0][aRow] = a4.x;
        As[nb][aCol + 1][aRow] = a4.y;
        As[nb][aCol + 2][aRow] = a4.z;
        As[nb][aCol + 3][aRow] = a4.w;
        Bs[nb][bCol + 0][bRow] = b4.x;
        Bs[nb][bCol + 1][bRow] = b4.y;
        Bs[nb][bCol + 2][bRow] = b4.z;
        Bs[nb][bCol + 3][bRow] = b4.w;
        __syncthreads();
        buf = nb;
    }
    #pragma unroll
    for (int k = 0; k < BK; k++)
        mm_step(&As[buf][k][threadRow * TM], &Bs[buf][k][threadCol * TN], acc);

    // Epilogue: C = s(n) * (acc + bias[n]). For the QKV call, scale_q_cols=1
    // folds the reference's q-scaling into columns [0, DIM): the reference
    // computes q = (x@Wq^T + b_q) * 512^-0.5, i.e. scale applied AFTER bias,
    // which matches s*(acc+bias).
    #pragma unroll
    for (int i = 0; i < TM; i++) {
        const int m = cRow * BM + threadRow * TM + i;
        #pragma unroll
        for (int j = 0; j < TN; j += 4) {
            const int n = cCol * BN + threadCol * TN + j;
            const float s = (scale_q_cols && n < DIM)
                          ? alpha * 0.04419417382415922f  // 512^-0.5
                          : alpha;
            float4 o;
            if (bias) {
                o.x = s * (acc[i][j + 0] + bias[n + 0]);
                o.y = s * (acc[i][j + 1] + bias[n + 1]);
                o.z = s * (acc[i][j + 2] + bias[n + 2]);
                o.w = s * (acc[i][j + 3] + bias[n + 3]);
            } else {
                o.x = s * acc[i][j + 0];
                o.y = s * acc[i][j + 1];
                o.z = s * acc[i][j + 2];
                o.w = s * acc[i][j + 3];
            }
            *reinterpret_cast<float4*>(&C[(long)m * ldc + n]) = o;
        }
    }
}

// ---------------------------------------------------------------------------
// NN: C[m,n] = sum_k A[m,k] * B[k,n]
// A: [M,K] row-major (lda), B: [K,N] row-major (ldb), C: [M,N] (ldc)
// ---------------------------------------------------------------------------
__global__ __launch_bounds__(256, 2)
void sgemm_nn(int M, int N, int K,
              const float* __restrict__ A, int lda, long strideA,
              const float* __restrict__ B, int ldb, long strideB,
              float* __restrict__ C, int ldc, long strideC)
{
    const int bz = blockIdx.z;
    A += bz * strideA;
    B += bz * strideB;
    C += bz * strideC;

    const int cCol = blockIdx.x;
    const int cRow = blockIdx.y;

    __shared__ __align__(16) float As[2][BK][BM + 4];
    __shared__ __align__(16) float Bs[2][BK][BN];     // pitch 512B (16B mult)

    const int tid = threadIdx.x;
    const int threadCol = tid % (BN / TN);
    const int threadRow = tid / (BN / TN);

    const int aRow = tid >> 1;
    const int aCol = (tid & 1) * 4;
    const int bRow = tid >> 5;          // 0..7 (k within tile)
    const int bCol = (tid & 31) * 4;    // 0..124

    const float* Aptr = A + (long)(cRow * BM + aRow) * lda + aCol;
    const float* Bptr = B + (long)bRow * ldb + cCol * BN + bCol;

    float acc[TM][TN];
    #pragma unroll
    for (int i = 0; i < TM; i++)
        #pragma unroll
        for (int j = 0; j < TN; j++) acc[i][j] = 0.0f;

    float4 a4 = *reinterpret_cast<const float4*>(Aptr);
    float4 b4 = *reinterpret_cast<const float4*>(Bptr);
    As[0][aCol + 0][aRow] = a4.x;
    As[0][aCol + 1][aRow] = a4.y;
    As[0][aCol + 2][aRow] = a4.z;
    As[0][aCol + 3][aRow] = a4.w;
    *reinterpret_cast<float4*>(&Bs[0][bRow][bCol]) = b4;
    __syncthreads();

    int buf = 0;
    for (int k0 = BK; k0 < K; k0 += BK) {
        Aptr += BK;
        Bptr += (long)BK * ldb;
        a4 = *reinterpret_cast<const float4*>(Aptr);
        b4 = *reinterpret_cast<const float4*>(Bptr);

        #pragma unroll
        for (int k = 0; k < BK; k++)
            mm_step(&As[buf][k][threadRow * TM], &Bs[buf][k][threadCol * TN], acc);

        const int nb = buf ^ 1;
        As[nb][aCol + 0][aRow] = a4.x;
        As[nb][aCol + 1][aRow] = a4.y;
        As[nb][aCol + 2][aRow] = a4.z;
        As[nb][aCol + 3][aRow] = a4.w;
        *reinterpret_cast<float4*>(&Bs[nb][bRow][bCol]) = b4;
        __syncthreads();
        buf = nb;
    }
    #pragma unroll
    for (int k = 0; k < BK; k++)
        mm_step(&As[buf][k][threadRow * TM], &Bs[buf][k][threadCol * TN], acc);

    #pragma unroll
    for (int i = 0; i < TM; i++) {
        const int m = cRow * BM + threadRow * TM + i;
        #pragma unroll
        for (int j = 0; j < TN; j += 4) {
            const int n = cCol * BN + threadCol * TN + j;
            float4 o;
            o.x = acc[i][j + 0];
            o.y = acc[i][j + 1];
            o.z = acc[i][j + 2];
            o.w = acc[i][j + 3];
            *reinterpret_cast<float4*>(&C[(long)m * ldc + n]) = o;
        }
    }
}

// ---------------------------------------------------------------------------
// Row softmax over SEQ=2048 elements, in place. One block (256 thr) per row.
// ---------------------------------------------------------------------------
__global__ __launch_bounds__(256)
void softmax_rows(float* __restrict__ S)
{
    float* row = S + (long)blockIdx.x * SEQ;
    const int tid = threadIdx.x;
    const int lane = tid & 31;
    const int warp = tid >> 5;
    __shared__ float red[8];
    __shared__ float bcast;

    float4 v0 = reinterpret_cast<float4*>(row)[tid];
    float4 v1 = reinterpret_cast<float4*>(row)[tid + 256];

    // --- max reduce ---
    float m = fmaxf(fmaxf(fmaxf(v0.x, v0.y), fmaxf(v0.z, v0.w)),
                    fmaxf(fmaxf(v1.x, v1.y), fmaxf(v1.z, v1.w)));
    #pragma unroll
    for (int o = 16; o > 0; o >>= 1)
        m = fmaxf(m, __shfl_xor_sync(0xffffffffu, m, o));
    if (lane == 0) red[warp] = m;
    __syncthreads();
    if (warp == 0) {
        float t = red[lane & 7];
        #pragma unroll
        for (int o = 4; o > 0; o >>= 1)
            t = fmaxf(t, __shfl_xor_sync(0xffffffffu, t, o));
        if (lane == 0) bcast = t;
    }
    __syncthreads();
    m = bcast;

    // --- exp + sum reduce ---
    v0.x = __expf(v0.x - m); v0.y = __expf(v0.y - m);
    v0.z = __expf(v0.z - m); v0.w = __expf(v0.w - m);
    v1.x = __expf(v1.x - m); v1.y = __expf(v1.y - m);
    v1.z = __expf(v1.z - m); v1.w = __expf(v1.w - m);
    float s = (v0.x + v0.y + v0.z + v0.w) + (v1.x + v1.y + v1.z + v1.w);
    #pragma unroll
    for (int o = 16; o > 0; o >>= 1)
        s += __shfl_xor_sync(0xffffffffu, s, o);
    __syncthreads();
    if (lane == 0) red[warp] = s;
    __syncthreads();
    if (warp == 0) {
        float t = red[lane & 7];
        #pragma unroll
        for (int o = 4; o > 0; o >>= 1)
            t += __shfl_xor_sync(0xffffffffu, t, o);
        if (lane == 0) bcast = t;
    }
    __syncthreads();
    const float inv = 1.0f / bcast;

    v0.x *= inv; v0.y *= inv; v0.z *= inv; v0.w *= inv;
    v1.x *= inv; v1.y *= inv; v1.z *= inv; v1.w *= inv;
    reinterpret_cast<float4*>(row)[tid] = v0;
    reinterpret_cast<float4*>(row)[tid + 256] = v1;
}

// ---------------------------------------------------------------------------
// Launch
// ---------------------------------------------------------------------------
extern "C" void kernel_launch(void* const* d_in, const int* in_sizes, int n_in,
                              void* d_out, int out_size)
{
    const float* x      = (const float*)d_in[0];  // [4,2048,512]
    const float* qkv_w  = (const float*)d_in[1];  // [1536,512]
    const float* qkv_b  = (const float*)d_in[2];  // [1536]
    const float* out_w  = (const float*)d_in[3];  // [512,512]
    const float* out_b  = (const float*)d_in[4];  // [512]
    float* out = (float*)d_out;                   // [4,2048,512]

    float *qkv, *scores, *attn;
    cudaGetSymbolAddress((void**)&qkv, g_qkv);
    cudaGetSymbolAddress((void**)&scores, g_scores);
    cudaGetSymbolAddress((void**)&attn, g_attn);

    const int M  = BATCH * SEQ;       // 8192
    const int D3 = 3 * DIM;           // 1536

    // 1) QKV projection (+bias); q columns [0,DIM) pre-scaled by 512^-0.5
    sgemm_nt<<<dim3(D3 / BN, M / BM, 1), 256>>>(
        M, D3, DIM,
        x, DIM, 0L,
        qkv_w, DIM, 0L,
        qkv, D3, 0L,
        qkv_b, 1.0f, /*scale_q_cols=*/1);

    // 2) Scores: per batch, q_scaled @ k^T -> g_scores [b,2048,2048]
    sgemm_nt<<<dim3(SEQ / BN, SEQ / BM, BATCH), 256>>>(
        SEQ, SEQ, DIM,
        qkv + 0,   D3, (long)SEQ * D3,     // q (already scaled)
        qkv + DIM, D3, (long)SEQ * D3,     // k
        scores, SEQ, (long)SEQ * SEQ,
        nullptr, 1.0f, 0);

    // 3) Softmax in place over last dim
    softmax_rows<<<BATCH * SEQ, 256>>>(scores);

    // 4) attn @ v -> g_attn [b,2048,512]
    sgemm_nn<<<dim3(DIM / BN, SEQ / BM, BATCH), 256>>>(
        SEQ, DIM, SEQ,
        scores, SEQ, (long)SEQ * SEQ,
        qkv + 2 * DIM, D3, (long)SEQ * D3, // v
        attn, DIM, (long)SEQ * DIM);

    // 5) Output projection: [8192,512] @ [512,512]^T + bias -> d_out
    sgemm_nt<<<dim3(DIM / BN, M / BM, 1), 256>>>(
        M, DIM, DIM,
        attn, DIM, 0L,
        out_w, DIM, 0L,
        out, DIM, 0L,
        out_b, 1.0f, 0);
}

// round 9
// speedup vs baseline: 1.1421x; 1.1421x over previous
#include <cuda_runtime.h>
#include <math_constants.h>

// Problem constants: B=4, S=2048, D=512
#define BATCH 4
#define SEQ   2048
#define DIM   512

// Scratch (device globals — allocation-free per harness rules)
__device__ float g_qkv[BATCH * SEQ * 3 * DIM];     // 48 MiB: [b, s, 3D] (q|k|v)
__device__ float g_scores[BATCH * SEQ * SEQ];      // 64 MiB: [b, q, k]
__device__ float g_attn[BATCH * SEQ * DIM];        // 16 MiB: [b, s, D]

// ---------------------------------------------------------------------------
// Double-buffered SGEMM, 128x128 block tile, BK=8, 256 threads, 8x8/thread.
// Warp lane grid remapped 2x16 -> 4x8 (warp tile 32x64) to cut unique smem
// bytes per warp per k-step from ~640B to 384B (measured L1 was 78.5%,
// fma 53.5% -> smem-crossbar bound).
// ---------------------------------------------------------------------------
#define BM 128
#define BN 128
#define BK 8
#define TM 8
#define TN 8

__device__ __forceinline__ void mm_step(
    const float* __restrict__ AsRow, const float* __restrict__ BsRow,
    float acc[TM][TN])
{
    const float4 m0 = *reinterpret_cast<const float4*>(AsRow);
    const float4 m1 = *reinterpret_cast<const float4*>(AsRow + 4);
    const float4 n0 = *reinterpret_cast<const float4*>(BsRow);
    const float4 n1 = *reinterpret_cast<const float4*>(BsRow + 4);
    const float regM[TM] = {m0.x, m0.y, m0.z, m0.w, m1.x, m1.y, m1.z, m1.w};
    const float regN[TN] = {n0.x, n0.y, n0.z, n0.w, n1.x, n1.y, n1.z, n1.w};
    #pragma unroll
    for (int i = 0; i < TM; i++)
        #pragma unroll
        for (int j = 0; j < TN; j++)
            acc[i][j] += regM[i] * regN[j];
}

// Lane mapping: 8 warps in a 4(M) x 2(N) grid; each warp 32x64 (lanes 4x8 of 8x8)
__device__ __forceinline__ void lane_map(int tid, int& row0, int& col0)
{
    const int warp = tid >> 5;
    const int lane = tid & 31;
    const int warp_m = warp & 3;        // 0..3  -> 4 * 32 = 128 rows
    const int warp_n = warp >> 2;       // 0..1  -> 2 * 64 = 128 cols
    row0 = warp_m * 32 + (lane & 3) * TM;   // 4 distinct row groups / warp
    col0 = warp_n * 64 + (lane >> 2) * TN;  // 8 distinct col groups / warp
}

// ---------------------------------------------------------------------------
// NT: C[m,n] = s(n) * (sum_k A[m,k] * B[n,k] + bias[n])
// s(n) = alpha * (scale_q_cols && n < DIM ? 512^-0.5 : 1)
// ---------------------------------------------------------------------------
__global__ __launch_bounds__(256, 2)
void sgemm_nt(int M, int N, int K,
              const float* __restrict__ A, int lda, long strideA,
              const float* __restrict__ B, int ldb, long strideB,
              float* __restrict__ C, int ldc, long strideC,
              const float* __restrict__ bias, float alpha, int scale_q_cols)
{
    const int bz = blockIdx.z;
    A += bz * strideA;
    B += bz * strideB;
    C += bz * strideC;

    const int cCol = blockIdx.x;  // N tile
    const int cRow = blockIdx.y;  // M tile

    __shared__ __align__(16) float As[2][BK][BM + 4];  // pitch 528B (16B mult)
    __shared__ __align__(16) float Bs[2][BK][BN + 4];

    const int tid = threadIdx.x;
    int row0, col0;
    lane_map(tid, row0, col0);

    const int aRow = tid >> 1;          // 0..127
    const int aCol = (tid & 1) * 4;     // 0 or 4
    const int bRow = tid >> 1;
    const int bCol = (tid & 1) * 4;

    const float* Aptr = A + (long)(cRow * BM + aRow) * lda + aCol;
    const float* Bptr = B + (long)(cCol * BN + bRow) * ldb + bCol;

    float acc[TM][TN];
    #pragma unroll
    for (int i = 0; i < TM; i++)
        #pragma unroll
        for (int j = 0; j < TN; j++) acc[i][j] = 0.0f;

    // prologue: tile 0 -> buffer 0
    float4 a4 = *reinterpret_cast<const float4*>(Aptr);
    float4 b4 = *reinterpret_cast<const float4*>(Bptr);
    As[0][aCol + 0][aRow] = a4.x;
    As[0][aCol + 1][aRow] = a4.y;
    As[0][aCol + 2][aRow] = a4.z;
    As[0][aCol + 3][aRow] = a4.w;
    Bs[0][bCol + 0][bRow] = b4.x;
    Bs[0][bCol + 1][bRow] = b4.y;
    Bs[0][bCol + 2][bRow] = b4.z;
    Bs[0][bCol + 3][bRow] = b4.w;
    __syncthreads();

    int buf = 0;
    for (int k0 = BK; k0 < K; k0 += BK) {
        Aptr += BK;
        Bptr += BK;
        a4 = *reinterpret_cast<const float4*>(Aptr);   // prefetch next tile
        b4 = *reinterpret_cast<const float4*>(Bptr);

        #pragma unroll
        for (int k = 0; k < BK; k++)
            mm_step(&As[buf][k][row0], &Bs[buf][k][col0], acc);

        const int nb = buf ^ 1;
        As[nb][aCol + 0][aRow] = a4.x;
        As[nb][aCol + 1][aRow] = a4.y;
        As[nb][aCol + 2][aRow] = a4.z;
        As[nb][aCol + 3][aRow] = a4.w;
        Bs[nb][bCol + 0][bRow] = b4.x;
        Bs[nb][bCol + 1][bRow] = b4.y;
        Bs[nb][bCol + 2][bRow] = b4.z;
        Bs[nb][bCol + 3][bRow] = b4.w;
        __syncthreads();
        buf = nb;
    }
    #pragma unroll
    for (int k = 0; k < BK; k++)
        mm_step(&As[buf][k][row0], &Bs[buf][k][col0], acc);

    // Epilogue: C = s(n) * (acc + bias[n]); q-scaling folded for cols [0,DIM)
    #pragma unroll
    for (int i = 0; i < TM; i++) {
        const int m = cRow * BM + row0 + i;
        #pragma unroll
        for (int j = 0; j < TN; j += 4) {
            const int n = cCol * BN + col0 + j;
            const float s = (scale_q_cols && n < DIM)
                          ? alpha * 0.04419417382415922f  // 512^-0.5
                          : alpha;
            float4 o;
            if (bias) {
                o.x = s * (acc[i][j + 0] + bias[n + 0]);
                o.y = s * (acc[i][j + 1] + bias[n + 1]);
                o.z = s * (acc[i][j + 2] + bias[n + 2]);
                o.w = s * (acc[i][j + 3] + bias[n + 3]);
            } else {
                o.x = s * acc[i][j + 0];
                o.y = s * acc[i][j + 1];
                o.z = s * acc[i][j + 2];
                o.w = s * acc[i][j + 3];
            }
            *reinterpret_cast<float4*>(&C[(long)m * ldc + n]) = o;
        }
    }
}

// ---------------------------------------------------------------------------
// NN: C[m,n] = sum_k A[m,k] * B[k,n]
// ---------------------------------------------------------------------------
__global__ __launch_bounds__(256, 2)
void sgemm_nn(int M, int N, int K,
              const float* __restrict__ A, int lda, long strideA,
              const float* __restrict__ B, int ldb, long strideB,
              float* __restrict__ C, int ldc, long strideC)
{
    const int bz = blockIdx.z;
    A += bz * strideA;
    B += bz * strideB;
    C += bz * strideC;

    const int cCol = blockIdx.x;
    const int cRow = blockIdx.y;

    __shared__ __align__(16) float As[2][BK][BM + 4];
    __shared__ __align__(16) float Bs[2][BK][BN];     // pitch 512B (16B mult)

    const int tid = threadIdx.x;
    int row0, col0;
    lane_map(tid, row0, col0);

    const int aRow = tid >> 1;
    const int aCol = (tid & 1) * 4;
    const int bRow = tid >> 5;          // 0..7 (k within tile)
    const int bCol = (tid & 31) * 4;    // 0..124

    const float* Aptr = A + (long)(cRow * BM + aRow) * lda + aCol;
    const float* Bptr = B + (long)bRow * ldb + cCol * BN + bCol;

    float acc[TM][TN];
    #pragma unroll
    for (int i = 0; i < TM; i++)
        #pragma unroll
        for (int j = 0; j < TN; j++) acc[i][j] = 0.0f;

    float4 a4 = *reinterpret_cast<const float4*>(Aptr);
    float4 b4 = *reinterpret_cast<const float4*>(Bptr);
    As[0][aCol + 0][aRow] = a4.x;
    As[0][aCol + 1][aRow] = a4.y;
    As[0][aCol + 2][aRow] = a4.z;
    As[0][aCol + 3][aRow] = a4.w;
    *reinterpret_cast<float4*>(&Bs[0][bRow][bCol]) = b4;
    __syncthreads();

    int buf = 0;
    for (int k0 = BK; k0 < K; k0 += BK) {
        Aptr += BK;
        Bptr += (long)BK * ldb;
        a4 = *reinterpret_cast<const float4*>(Aptr);
        b4 = *reinterpret_cast<const float4*>(Bptr);

        #pragma unroll
        for (int k = 0; k < BK; k++)
            mm_step(&As[buf][k][row0], &Bs[buf][k][col0], acc);

        const int nb = buf ^ 1;
        As[nb][aCol + 0][aRow] = a4.x;
        As[nb][aCol + 1][aRow] = a4.y;
        As[nb][aCol + 2][aRow] = a4.z;
        As[nb][aCol + 3][aRow] = a4.w;
        *reinterpret_cast<float4*>(&Bs[nb][bRow][bCol]) = b4;
        __syncthreads();
        buf = nb;
    }
    #pragma unroll
    for (int k = 0; k < BK; k++)
        mm_step(&As[buf][k][row0], &Bs[buf][k][col0], acc);

    #pragma unroll
    for (int i = 0; i < TM; i++) {
        const int m = cRow * BM + row0 + i;
        #pragma unroll
        for (int j = 0; j < TN; j += 4) {
            const int n = cCol * BN + col0 + j;
            float4 o;
            o.x = acc[i][j + 0];
            o.y = acc[i][j + 1];
            o.z = acc[i][j + 2];
            o.w = acc[i][j + 3];
            *reinterpret_cast<float4*>(&C[(long)m * ldc + n]) = o;
        }
    }
}

// ---------------------------------------------------------------------------
// Row softmax over SEQ=2048 elements, in place. One block (256 thr) per row.
// ---------------------------------------------------------------------------
__global__ __launch_bounds__(256)
void softmax_rows(float* __restrict__ S)
{
    float* row = S + (long)blockIdx.x * SEQ;
    const int tid = threadIdx.x;
    const int lane = tid & 31;
    const int warp = tid >> 5;
    __shared__ float red[8];
    __shared__ float bcast;

    float4 v0 = reinterpret_cast<float4*>(row)[tid];
    float4 v1 = reinterpret_cast<float4*>(row)[tid + 256];

    // --- max reduce ---
    float m = fmaxf(fmaxf(fmaxf(v0.x, v0.y), fmaxf(v0.z, v0.w)),
                    fmaxf(fmaxf(v1.x, v1.y), fmaxf(v1.z, v1.w)));
    #pragma unroll
    for (int o = 16; o > 0; o >>= 1)
        m = fmaxf(m, __shfl_xor_sync(0xffffffffu, m, o));
    if (lane == 0) red[warp] = m;
    __syncthreads();
    if (warp == 0) {
        float t = red[lane & 7];
        #pragma unroll
        for (int o = 4; o > 0; o >>= 1)
            t = fmaxf(t, __shfl_xor_sync(0xffffffffu, t, o));
        if (lane == 0) bcast = t;
    }
    __syncthreads();
    m = bcast;

    // --- exp + sum reduce ---
    v0.x = __expf(v0.x - m); v0.y = __expf(v0.y - m);
    v0.z = __expf(v0.z - m); v0.w = __expf(v0.w - m);
    v1.x = __expf(v1.x - m); v1.y = __expf(v1.y - m);
    v1.z = __expf(v1.z - m); v1.w = __expf(v1.w - m);
    float s = (v0.x + v0.y + v0.z + v0.w) + (v1.x + v1.y + v1.z + v1.w);
    #pragma unroll
    for (int o = 16; o > 0; o >>= 1)
        s += __shfl_xor_sync(0xffffffffu, s, o);
    __syncthreads();
    if (lane == 0) red[warp] = s;
    __syncthreads();
    if (warp == 0) {
        float t = red[lane & 7];
        #pragma unroll
        for (int o = 4; o > 0; o >>= 1)
            t += __shfl_xor_sync(0xffffffffu, t, o);
        if (lane == 0) bcast = t;
    }
    __syncthreads();
    const float inv = 1.0f / bcast;

    v0.x *= inv; v0.y *= inv; v0.z *= inv; v0.w *= inv;
    v1.x *= inv; v1.y *= inv; v1.z *= inv; v1.w *= inv;
    reinterpret_cast<float4*>(row)[tid] = v0;
    reinterpret_cast<float4*>(row)[tid + 256] = v1;
}

// ---------------------------------------------------------------------------
// Launch
// ---------------------------------------------------------------------------
extern "C" void kernel_launch(void* const* d_in, const int* in_sizes, int n_in,
                              void* d_out, int out_size)
{
    const float* x      = (const float*)d_in[0];  // [4,2048,512]
    const float* qkv_w  = (const float*)d_in[1];  // [1536,512]
    const float* qkv_b  = (const float*)d_in[2];  // [1536]
    const float* out_w  = (const float*)d_in[3];  // [512,512]
    const float* out_b  = (const float*)d_in[4];  // [512]
    float* out = (float*)d_out;                   // [4,2048,512]

    float *qkv, *scores, *attn;
    cudaGetSymbolAddress((void**)&qkv, g_qkv);
    cudaGetSymbolAddress((void**)&scores, g_scores);
    cudaGetSymbolAddress((void**)&attn, g_attn);

    const int M  = BATCH * SEQ;       // 8192
    const int D3 = 3 * DIM;           // 1536

    // 1) QKV projection (+bias); q columns [0,DIM) pre-scaled by 512^-0.5
    sgemm_nt<<<dim3(D3 / BN, M / BM, 1), 256>>>(
        M, D3, DIM,
        x, DIM, 0L,
        qkv_w, DIM, 0L,
        qkv, D3, 0L,
        qkv_b, 1.0f, /*scale_q_cols=*/1);

    // 2) Scores: per batch, q_scaled @ k^T -> g_scores [b,2048,2048]
    sgemm_nt<<<dim3(SEQ / BN, SEQ / BM, BATCH), 256>>>(
        SEQ, SEQ, DIM,
        qkv + 0,   D3, (long)SEQ * D3,     // q (already scaled)
        qkv + DIM, D3, (long)SEQ * D3,     // k
        scores, SEQ, (long)SEQ * SEQ,
        nullptr, 1.0f, 0);

    // 3) Softmax in place over last dim
    softmax_rows<<<BATCH * SEQ, 256>>>(scores);

    // 4) attn @ v -> g_attn [b,2048,512]
    sgemm_nn<<<dim3(DIM / BN, SEQ / BM, BATCH), 256>>>(
        SEQ, DIM, SEQ,
        scores, SEQ, (long)SEQ * SEQ,
        qkv + 2 * DIM, D3, (long)SEQ * D3, // v
        attn, DIM, (long)SEQ * DIM);

    // 5) Output projection: [8192,512] @ [512,512]^T + bias -> d_out
    sgemm_nt<<<dim3(DIM / BN, M / BM, 1), 256>>>(
        M, DIM, DIM,
        attn, DIM, 0L,
        out_w, DIM, 0L,
        out, DIM, 0L,
        out_b, 1.0f, 0);
}

// round 10
// speedup vs baseline: 1.2646x; 1.1072x over previous
#include <cuda_runtime.h>

// Problem constants: B=4, S=2048, D=512
#define BATCH 4
#define SEQ   2048
#define DIM   512

// Scratch (device globals — allocation-free per harness rules)
__device__ float g_qkv[BATCH * SEQ * 3 * DIM];     // 48 MiB: [b, s, 3D] (q|k|v)
__device__ float g_scores[BATCH * SEQ * SEQ];      // 64 MiB: [b, q, k]
__device__ float g_attn[BATCH * SEQ * DIM];        // 16 MiB: [b, s, D]

// ---------------------------------------------------------------------------
// 3xTF32 GEMM via mma.sync.m16n8k8 (fp32-accurate: hi*hi + lo*hi + hi*lo).
// 128x128 block tile, BK=8, 256 threads (8 warps as 4Mx2N), warp tile 32x64.
// Two-stage smem; smem holds tf32 hi/lo planes, k-major rows, PITCH=136 words
// (136 % 32 == 8 -> fragment LDS banks = 8*tig + g + const: all 32 distinct).
// ---------------------------------------------------------------------------
#define BM 128
#define BN 128
#define BK 8
#define PITCH 136

__device__ __forceinline__ unsigned f2tf32(float x)
{
    unsigned r;
    asm("cvt.rna.tf32.f32 %0, %1;" : "=r"(r) : "f"(x));
    return r;
}

__device__ __forceinline__ void split_tf32(float x, unsigned& hi, unsigned& lo)
{
    hi = f2tf32(x);
    lo = f2tf32(x - __uint_as_float(hi));
}

__device__ __forceinline__ void mma8(float* c,
    unsigned a0, unsigned a1, unsigned a2, unsigned a3,
    unsigned b0, unsigned b1)
{
    asm volatile(
        "mma.sync.aligned.m16n8k8.row.col.f32.tf32.tf32.f32 "
        "{%0,%1,%2,%3}, {%4,%5,%6,%7}, {%8,%9}, {%0,%1,%2,%3};\n"
        : "+f"(c[0]), "+f"(c[1]), "+f"(c[2]), "+f"(c[3])
        : "r"(a0), "r"(a1), "r"(a2), "r"(a3), "r"(b0), "r"(b1));
}

// One BK=8 slice: 2 m-tiles x 8 n-tiles of m16n8k8, x3 (hi/lo split).
__device__ __forceinline__ void mma_block(
    const unsigned* __restrict__ AH, const unsigned* __restrict__ AL,
    const unsigned* __restrict__ BH, const unsigned* __restrict__ BL,
    int warpM0, int warpN0, int g, int tig, float acc[2][8][4])
{
    unsigned ah[2][4], al[2][4];
    #pragma unroll
    for (int mt = 0; mt < 2; mt++) {
        const int m = warpM0 + mt * 16 + g;
        ah[mt][0] = AH[ tig      * PITCH + m];
        ah[mt][1] = AH[ tig      * PITCH + m + 8];
        ah[mt][2] = AH[(tig + 4) * PITCH + m];
        ah[mt][3] = AH[(tig + 4) * PITCH + m + 8];
        al[mt][0] = AL[ tig      * PITCH + m];
        al[mt][1] = AL[ tig      * PITCH + m + 8];
        al[mt][2] = AL[(tig + 4) * PITCH + m];
        al[mt][3] = AL[(tig + 4) * PITCH + m + 8];
    }
    #pragma unroll
    for (int nt = 0; nt < 8; nt++) {
        const int n = warpN0 + nt * 8 + g;
        const unsigned bh0 = BH[ tig      * PITCH + n];
        const unsigned bh1 = BH[(tig + 4) * PITCH + n];
        const unsigned bl0 = BL[ tig      * PITCH + n];
        const unsigned bl1 = BL[(tig + 4) * PITCH + n];
        #pragma unroll
        for (int mt = 0; mt < 2; mt++) {
            mma8(acc[mt][nt], ah[mt][0], ah[mt][1], ah[mt][2], ah[mt][3], bh0, bh1);
            mma8(acc[mt][nt], al[mt][0], al[mt][1], al[mt][2], al[mt][3], bh0, bh1);
            mma8(acc[mt][nt], ah[mt][0], ah[mt][1], ah[mt][2], ah[mt][3], bl0, bl1);
        }
    }
}

// ---------------------------------------------------------------------------
// NT: C[m,n] = s(n) * (sum_k A[m,k] * B[n,k] + bias[n])
// A: [M,K] rm (lda), B: [N,K] rm (ldb). s(n)=alpha*(scale_q && n<DIM ? 512^-.5 : 1)
// ---------------------------------------------------------------------------
__global__ __launch_bounds__(256, 2)
void gemm_nt_tf32(int M, int N, int K,
                  const float* __restrict__ A, int lda, long strideA,
                  const float* __restrict__ B, int ldb, long strideB,
                  float* __restrict__ C, int ldc, long strideC,
                  const float* __restrict__ bias, float alpha, int scale_q_cols)
{
    A += blockIdx.z * strideA;
    B += blockIdx.z * strideB;
    C += blockIdx.z * strideC;
    const int cCol = blockIdx.x, cRow = blockIdx.y;

    __shared__ unsigned AsH[2][BK * PITCH], AsL[2][BK * PITCH];
    __shared__ unsigned BsH[2][BK * PITCH], BsL[2][BK * PITCH];

    const int tid  = threadIdx.x;
    const int warp = tid >> 5, lane = tid & 31;
    const int warpM0 = (warp & 3) * 32, warpN0 = (warp >> 2) * 64;
    const int g = lane >> 2, tig = lane & 3;

    const int aRow = tid >> 1, aCol = (tid & 1) * 4;   // 128 rows x 2 float4
    const float* Aptr = A + (long)(cRow * BM + aRow) * lda + aCol;
    const float* Bptr = B + (long)(cCol * BN + aRow) * ldb + aCol;

    float acc[2][8][4];
    #pragma unroll
    for (int mt = 0; mt < 2; mt++)
        #pragma unroll
        for (int nt = 0; nt < 8; nt++)
            #pragma unroll
            for (int r = 0; r < 4; r++) acc[mt][nt][r] = 0.0f;

    float4 a4 = *reinterpret_cast<const float4*>(Aptr);
    float4 b4 = *reinterpret_cast<const float4*>(Bptr);
    {
        unsigned h, l;
        split_tf32(a4.x, h, l); AsH[0][(aCol+0)*PITCH + aRow] = h; AsL[0][(aCol+0)*PITCH + aRow] = l;
        split_tf32(a4.y, h, l); AsH[0][(aCol+1)*PITCH + aRow] = h; AsL[0][(aCol+1)*PITCH + aRow] = l;
        split_tf32(a4.z, h, l); AsH[0][(aCol+2)*PITCH + aRow] = h; AsL[0][(aCol+2)*PITCH + aRow] = l;
        split_tf32(a4.w, h, l); AsH[0][(aCol+3)*PITCH + aRow] = h; AsL[0][(aCol+3)*PITCH + aRow] = l;
        split_tf32(b4.x, h, l); BsH[0][(aCol+0)*PITCH + aRow] = h; BsL[0][(aCol+0)*PITCH + aRow] = l;
        split_tf32(b4.y, h, l); BsH[0][(aCol+1)*PITCH + aRow] = h; BsL[0][(aCol+1)*PITCH + aRow] = l;
        split_tf32(b4.z, h, l); BsH[0][(aCol+2)*PITCH + aRow] = h; BsL[0][(aCol+2)*PITCH + aRow] = l;
        split_tf32(b4.w, h, l); BsH[0][(aCol+3)*PITCH + aRow] = h; BsL[0][(aCol+3)*PITCH + aRow] = l;
    }
    __syncthreads();

    int buf = 0;
    for (int k0 = BK; k0 < K; k0 += BK) {
        Aptr += BK;
        Bptr += BK;
        a4 = *reinterpret_cast<const float4*>(Aptr);
        b4 = *reinterpret_cast<const float4*>(Bptr);

        mma_block(AsH[buf], AsL[buf], BsH[buf], BsL[buf], warpM0, warpN0, g, tig, acc);

        const int nb = buf ^ 1;
        unsigned h, l;
        split_tf32(a4.x, h, l); AsH[nb][(aCol+0)*PITCH + aRow] = h; AsL[nb][(aCol+0)*PITCH + aRow] = l;
        split_tf32(a4.y, h, l); AsH[nb][(aCol+1)*PITCH + aRow] = h; AsL[nb][(aCol+1)*PITCH + aRow] = l;
        split_tf32(a4.z, h, l); AsH[nb][(aCol+2)*PITCH + aRow] = h; AsL[nb][(aCol+2)*PITCH + aRow] = l;
        split_tf32(a4.w, h, l); AsH[nb][(aCol+3)*PITCH + aRow] = h; AsL[nb][(aCol+3)*PITCH + aRow] = l;
        split_tf32(b4.x, h, l); BsH[nb][(aCol+0)*PITCH + aRow] = h; BsL[nb][(aCol+0)*PITCH + aRow] = l;
        split_tf32(b4.y, h, l); BsH[nb][(aCol+1)*PITCH + aRow] = h; BsL[nb][(aCol+1)*PITCH + aRow] = l;
        split_tf32(b4.z, h, l); BsH[nb][(aCol+2)*PITCH + aRow] = h; BsL[nb][(aCol+2)*PITCH + aRow] = l;
        split_tf32(b4.w, h, l); BsH[nb][(aCol+3)*PITCH + aRow] = h; BsL[nb][(aCol+3)*PITCH + aRow] = l;
        __syncthreads();
        buf = nb;
    }
    mma_block(AsH[buf], AsL[buf], BsH[buf], BsL[buf], warpM0, warpN0, g, tig, acc);

    // Epilogue: C = s(n) * (acc + bias[n]); q-scaling folded for cols [0,DIM)
    #pragma unroll
    for (int mt = 0; mt < 2; mt++) {
        const int m0 = cRow * BM + warpM0 + mt * 16 + g;
        #pragma unroll
        for (int nt = 0; nt < 8; nt++) {
            const int n = cCol * BN + warpN0 + nt * 8 + 2 * tig;
            const float s = (scale_q_cols && n < DIM)
                          ? alpha * 0.04419417382415922f  // 512^-0.5
                          : alpha;
            float b0 = 0.0f, b1 = 0.0f;
            if (bias) { b0 = bias[n]; b1 = bias[n + 1]; }
            float2 o0, o1;
            o0.x = s * (acc[mt][nt][0] + b0);
            o0.y = s * (acc[mt][nt][1] + b1);
            o1.x = s * (acc[mt][nt][2] + b0);
            o1.y = s * (acc[mt][nt][3] + b1);
            *reinterpret_cast<float2*>(&C[(long)m0 * ldc + n]) = o0;
            *reinterpret_cast<float2*>(&C[(long)(m0 + 8) * ldc + n]) = o1;
        }
    }
}

// ---------------------------------------------------------------------------
// NN: C[m,n] = sum_k A[m,k] * B[k,n];  A: [M,K] rm (lda), B: [K,N] rm (ldb)
// ---------------------------------------------------------------------------
__global__ __launch_bounds__(256, 2)
void gemm_nn_tf32(int M, int N, int K,
                  const float* __restrict__ A, int lda, long strideA,
                  const float* __restrict__ B, int ldb, long strideB,
                  float* __restrict__ C, int ldc, long strideC)
{
    A += blockIdx.z * strideA;
    B += blockIdx.z * strideB;
    C += blockIdx.z * strideC;
    const int cCol = blockIdx.x, cRow = blockIdx.y;

    __shared__ unsigned AsH[2][BK * PITCH], AsL[2][BK * PITCH];
    __shared__ unsigned BsH[2][BK * PITCH], BsL[2][BK * PITCH];

    const int tid  = threadIdx.x;
    const int warp = tid >> 5, lane = tid & 31;
    const int warpM0 = (warp & 3) * 32, warpN0 = (warp >> 2) * 64;
    const int g = lane >> 2, tig = lane & 3;

    const int aRow = tid >> 1, aCol = (tid & 1) * 4;
    const int bRow = tid >> 5, bCol = (tid & 31) * 4;   // B: 8 k-rows x 128 n

    const float* Aptr = A + (long)(cRow * BM + aRow) * lda + aCol;
    const float* Bptr = B + (long)bRow * ldb + cCol * BN + bCol;

    float acc[2][8][4];
    #pragma unroll
    for (int mt = 0; mt < 2; mt++)
        #pragma unroll
        for (int nt = 0; nt < 8; nt++)
            #pragma unroll
            for (int r = 0; r < 4; r++) acc[mt][nt][r] = 0.0f;

    float4 a4 = *reinterpret_cast<const float4*>(Aptr);
    float4 b4 = *reinterpret_cast<const float4*>(Bptr);
    {
        unsigned h, l;
        split_tf32(a4.x, h, l); AsH[0][(aCol+0)*PITCH + aRow] = h; AsL[0][(aCol+0)*PITCH + aRow] = l;
        split_tf32(a4.y, h, l); AsH[0][(aCol+1)*PITCH + aRow] = h; AsL[0][(aCol+1)*PITCH + aRow] = l;
        split_tf32(a4.z, h, l); AsH[0][(aCol+2)*PITCH + aRow] = h; AsL[0][(aCol+2)*PITCH + aRow] = l;
        split_tf32(a4.w, h, l); AsH[0][(aCol+3)*PITCH + aRow] = h; AsL[0][(aCol+3)*PITCH + aRow] = l;
        unsigned h0,h1,h2,h3,l0,l1,l2,l3;
        split_tf32(b4.x, h0, l0); split_tf32(b4.y, h1, l1);
        split_tf32(b4.z, h2, l2); split_tf32(b4.w, h3, l3);
        *reinterpret_cast<uint4*>(&BsH[0][bRow * PITCH + bCol]) = make_uint4(h0, h1, h2, h3);
        *reinterpret_cast<uint4*>(&BsL[0][bRow * PITCH + bCol]) = make_uint4(l0, l1, l2, l3);
    }
    __syncthreads();

    int buf = 0;
    for (int k0 = BK; k0 < K; k0 += BK) {
        Aptr += BK;
        Bptr += (long)BK * ldb;
        a4 = *reinterpret_cast<const float4*>(Aptr);
        b4 = *reinterpret_cast<const float4*>(Bptr);

        mma_block(AsH[buf], AsL[buf], BsH[buf], BsL[buf], warpM0, warpN0, g, tig, acc);

        const int nb = buf ^ 1;
        unsigned h, l;
        split_tf32(a4.x, h, l); AsH[nb][(aCol+0)*PITCH + aRow] = h; AsL[nb][(aCol+0)*PITCH + aRow] = l;
        split_tf32(a4.y, h, l); AsH[nb][(aCol+1)*PITCH + aRow] = h; AsL[nb][(aCol+1)*PITCH + aRow] = l;
        split_tf32(a4.z, h, l); AsH[nb][(aCol+2)*PITCH + aRow] = h; AsL[nb][(aCol+2)*PITCH + aRow] = l;
        split_tf32(a4.w, h, l); AsH[nb][(aCol+3)*PITCH + aRow] = h; AsL[nb][(aCol+3)*PITCH + aRow] = l;
        unsigned h0,h1,h2,h3,l0,l1,l2,l3;
        split_tf32(b4.x, h0, l0); split_tf32(b4.y, h1, l1);
        split_tf32(b4.z, h2, l2); split_tf32(b4.w, h3, l3);
        *reinterpret_cast<uint4*>(&BsH[nb][bRow * PITCH + bCol]) = make_uint4(h0, h1, h2, h3);
        *reinterpret_cast<uint4*>(&BsL[nb][bRow * PITCH + bCol]) = make_uint4(l0, l1, l2, l3);
        __syncthreads();
        buf = nb;
    }
    mma_block(AsH[buf], AsL[buf], BsH[buf], BsL[buf], warpM0, warpN0, g, tig, acc);

    #pragma unroll
    for (int mt = 0; mt < 2; mt++) {
        const int m0 = cRow * BM + warpM0 + mt * 16 + g;
        #pragma unroll
        for (int nt = 0; nt < 8; nt++) {
            const int n = cCol * BN + warpN0 + nt * 8 + 2 * tig;
            float2 o0, o1;
            o0.x = acc[mt][nt][0];
            o0.y = acc[mt][nt][1];
            o1.x = acc[mt][nt][2];
            o1.y = acc[mt][nt][3];
            *reinterpret_cast<float2*>(&C[(long)m0 * ldc + n]) = o0;
            *reinterpret_cast<float2*>(&C[(long)(m0 + 8) * ldc + n]) = o1;
        }
    }
}

// ---------------------------------------------------------------------------
// Row softmax over SEQ=2048 elements, in place. One block (256 thr) per row.
// ---------------------------------------------------------------------------
__global__ __launch_bounds__(256)
void softmax_rows(float* __restrict__ S)
{
    float* row = S + (long)blockIdx.x * SEQ;
    const int tid = threadIdx.x;
    const int lane = tid & 31;
    const int warp = tid >> 5;
    __shared__ float red[8];
    __shared__ float bcast;

    float4 v0 = reinterpret_cast<float4*>(row)[tid];
    float4 v1 = reinterpret_cast<float4*>(row)[tid + 256];

    float m = fmaxf(fmaxf(fmaxf(v0.x, v0.y), fmaxf(v0.z, v0.w)),
                    fmaxf(fmaxf(v1.x, v1.y), fmaxf(v1.z, v1.w)));
    #pragma unroll
    for (int o = 16; o > 0; o >>= 1)
        m = fmaxf(m, __shfl_xor_sync(0xffffffffu, m, o));
    if (lane == 0) red[warp] = m;
    __syncthreads();
    if (warp == 0) {
        float t = red[lane & 7];
        #pragma unroll
        for (int o = 4; o > 0; o >>= 1)
            t = fmaxf(t, __shfl_xor_sync(0xffffffffu, t, o));
        if (lane == 0) bcast = t;
    }
    __syncthreads();
    m = bcast;

    v0.x = __expf(v0.x - m); v0.y = __expf(v0.y - m);
    v0.z = __expf(v0.z - m); v0.w = __expf(v0.w - m);
    v1.x = __expf(v1.x - m); v1.y = __expf(v1.y - m);
    v1.z = __expf(v1.z - m); v1.w = __expf(v1.w - m);
    float s = (v0.x + v0.y + v0.z + v0.w) + (v1.x + v1.y + v1.z + v1.w);
    #pragma unroll
    for (int o = 16; o > 0; o >>= 1)
        s += __shfl_xor_sync(0xffffffffu, s, o);
    __syncthreads();
    if (lane == 0) red[warp] = s;
    __syncthreads();
    if (warp == 0) {
        float t = red[lane & 7];
        #pragma unroll
        for (int o = 4; o > 0; o >>= 1)
            t += __shfl_xor_sync(0xffffffffu, t, o);
        if (lane == 0) bcast = t;
    }
    __syncthreads();
    const float inv = 1.0f / bcast;

    v0.x *= inv; v0.y *= inv; v0.z *= inv; v0.w *= inv;
    v1.x *= inv; v1.y *= inv; v1.z *= inv; v1.w *= inv;
    reinterpret_cast<float4*>(row)[tid] = v0;
    reinterpret_cast<float4*>(row)[tid + 256] = v1;
}

// ---------------------------------------------------------------------------
// Launch
// ---------------------------------------------------------------------------
extern "C" void kernel_launch(void* const* d_in, const int* in_sizes, int n_in,
                              void* d_out, int out_size)
{
    const float* x      = (const float*)d_in[0];  // [4,2048,512]
    const float* qkv_w  = (const float*)d_in[1];  // [1536,512]
    const float* qkv_b  = (const float*)d_in[2];  // [1536]
    const float* out_w  = (const float*)d_in[3];  // [512,512]
    const float* out_b  = (const float*)d_in[4];  // [512]
    float* out = (float*)d_out;                   // [4,2048,512]

    float *qkv, *scores, *attn;
    cudaGetSymbolAddress((void**)&qkv, g_qkv);
    cudaGetSymbolAddress((void**)&scores, g_scores);
    cudaGetSymbolAddress((void**)&attn, g_attn);

    const int M  = BATCH * SEQ;       // 8192
    const int D3 = 3 * DIM;           // 1536

    // 1) QKV projection (+bias); q columns [0,DIM) pre-scaled by 512^-0.5
    gemm_nt_tf32<<<dim3(D3 / BN, M / BM, 1), 256>>>(
        M, D3, DIM,
        x, DIM, 0L,
        qkv_w, DIM, 0L,
        qkv, D3, 0L,
        qkv_b, 1.0f, /*scale_q_cols=*/1);

    // 2) Scores: per batch, q_scaled @ k^T -> g_scores [b,2048,2048]
    gemm_nt_tf32<<<dim3(SEQ / BN, SEQ / BM, BATCH), 256>>>(
        SEQ, SEQ, DIM,
        qkv + 0,   D3, (long)SEQ * D3,     // q (already scaled)
        qkv + DIM, D3, (long)SEQ * D3,     // k
        scores, SEQ, (long)SEQ * SEQ,
        nullptr, 1.0f, 0);

    // 3) Softmax in place over last dim
    softmax_rows<<<BATCH * SEQ, 256>>>(scores);

    // 4) attn @ v -> g_attn [b,2048,512]
    gemm_nn_tf32<<<dim3(DIM / BN, SEQ / BM, BATCH), 256>>>(
        SEQ, DIM, SEQ,
        scores, SEQ, (long)SEQ * SEQ,
        qkv + 2 * DIM, D3, (long)SEQ * D3, // v
        attn, DIM, (long)SEQ * DIM);

    // 5) Output projection: [8192,512] @ [512,512]^T + bias -> d_out
    gemm_nt_tf32<<<dim3(DIM / BN, M / BM, 1), 256>>>(
        M, DIM, DIM,
        attn, DIM, 0L,
        out_w, DIM, 0L,
        out, DIM, 0L,
        out_b, 1.0f, 0);
}

// round 12
// speedup vs baseline: 1.3135x; 1.0387x over previous
#include <cuda_runtime.h>

// Problem constants: B=4, S=2048, D=512
#define BATCH 4
#define SEQ   2048
#define DIM   512

// Scratch (device globals — allocation-free per harness rules)
__device__ float g_qkv[BATCH * SEQ * 3 * DIM];     // 48 MiB: [b, s, 3D] (q|k|v)
__device__ float g_scores[BATCH * SEQ * SEQ];      // 64 MiB: [b, q, k]
__device__ float g_attn[BATCH * SEQ * DIM];        // 16 MiB: [b, s, D]

// ---------------------------------------------------------------------------
// 3xTF32 GEMM via mma.sync.m16n8k8 (fp32-accurate: hi*hi + lo*hi + hi*lo).
// 128x128 block tile, BK=16 (halve barriers/store bursts per FLOP vs BK=8;
// measured tensor 52.5%, issue 32.2% -> MMA pipe starved by per-iter
// overhead). 256 threads (8 warps as 4Mx2N), warp tile 32x64.
// Two-stage DYNAMIC smem (69.6KB); tf32 hi/lo planes, k-major, PITCH=136
// (136 % 32 == 8 -> fragment LDS banks all 32 distinct).
// ---------------------------------------------------------------------------
#define BM 128
#define BN 128
#define BK 16
#define PITCH 136
#define PLANE (BK * PITCH)                 // words per stage per plane
#define SMEM_WORDS (8 * PLANE)             // 4 planes x 2 stages
#define SMEM_BYTES (SMEM_WORDS * 4)        // 69632 B

__device__ __forceinline__ unsigned f2tf32(float x)
{
    unsigned r;
    asm("cvt.rna.tf32.f32 %0, %1;" : "=r"(r) : "f"(x));
    return r;
}

__device__ __forceinline__ void split_tf32(float x, unsigned& hi, unsigned& lo)
{
    hi = f2tf32(x);
    lo = f2tf32(x - __uint_as_float(hi));
}

__device__ __forceinline__ void mma8(float* c,
    unsigned a0, unsigned a1, unsigned a2, unsigned a3,
    unsigned b0, unsigned b1)
{
    asm volatile(
        "mma.sync.aligned.m16n8k8.row.col.f32.tf32.tf32.f32 "
        "{%0,%1,%2,%3}, {%4,%5,%6,%7}, {%8,%9}, {%0,%1,%2,%3};\n"
        : "+f"(c[0]), "+f"(c[1]), "+f"(c[2]), "+f"(c[3])
        : "r"(a0), "r"(a1), "r"(a2), "r"(a3), "r"(b0), "r"(b1));
}

// One k=8 slice: 2 m-tiles x 8 n-tiles of m16n8k8, x3 (hi/lo split).
// AH/AL/BH/BL point at the 8xPITCH k-slab to consume.
__device__ __forceinline__ void mma_block(
    const unsigned* __restrict__ AH, const unsigned* __restrict__ AL,
    const unsigned* __restrict__ BH, const unsigned* __restrict__ BL,
    int warpM0, int warpN0, int g, int tig, float acc[2][8][4])
{
    unsigned ah[2][4], al[2][4];
    #pragma unroll
    for (int mt = 0; mt < 2; mt++) {
        const int m = warpM0 + mt * 16 + g;
        ah[mt][0] = AH[ tig      * PITCH + m];
        ah[mt][1] = AH[ tig      * PITCH + m + 8];
        ah[mt][2] = AH[(tig + 4) * PITCH + m];
        ah[mt][3] = AH[(tig + 4) * PITCH + m + 8];
        al[mt][0] = AL[ tig      * PITCH + m];
        al[mt][1] = AL[ tig      * PITCH + m + 8];
        al[mt][2] = AL[(tig + 4) * PITCH + m];
        al[mt][3] = AL[(tig + 4) * PITCH + m + 8];
    }
    #pragma unroll
    for (int nt = 0; nt < 8; nt++) {
        const int n = warpN0 + nt * 8 + g;
        const unsigned bh0 = BH[ tig      * PITCH + n];
        const unsigned bh1 = BH[(tig + 4) * PITCH + n];
        const unsigned bl0 = BL[ tig      * PITCH + n];
        const unsigned bl1 = BL[(tig + 4) * PITCH + n];
        #pragma unroll
        for (int mt = 0; mt < 2; mt++) {
            mma8(acc[mt][nt], ah[mt][0], ah[mt][1], ah[mt][2], ah[mt][3], bh0, bh1);
            mma8(acc[mt][nt], al[mt][0], al[mt][1], al[mt][2], al[mt][3], bh0, bh1);
            mma8(acc[mt][nt], ah[mt][0], ah[mt][1], ah[mt][2], ah[mt][3], bl0, bl1);
        }
    }
}

// Store one float4 into a k-major plane pair at (col0..col0+3, row).
__device__ __forceinline__ void store_kmajor4(
    unsigned* __restrict__ H, unsigned* __restrict__ L,
    int col0, int row, float4 v)
{
    unsigned h, l;
    split_tf32(v.x, h, l); H[(col0 + 0) * PITCH + row] = h; L[(col0 + 0) * PITCH + row] = l;
    split_tf32(v.y, h, l); H[(col0 + 1) * PITCH + row] = h; L[(col0 + 1) * PITCH + row] = l;
    split_tf32(v.z, h, l); H[(col0 + 2) * PITCH + row] = h; L[(col0 + 2) * PITCH + row] = l;
    split_tf32(v.w, h, l); H[(col0 + 3) * PITCH + row] = h; L[(col0 + 3) * PITCH + row] = l;
}

// ---------------------------------------------------------------------------
// NT: C[m,n] = s(n) * (sum_k A[m,k] * B[n,k] + bias[n])
// A: [M,K] rm (lda), B: [N,K] rm (ldb). s(n)=alpha*(scale_q && n<DIM ? 512^-.5 : 1)
// K % 16 == 0.
// ---------------------------------------------------------------------------
__global__ __launch_bounds__(256, 2)
void gemm_nt_tf32(int M, int N, int K,
                  const float* __restrict__ A, int lda, long strideA,
                  const float* __restrict__ B, int ldb, long strideB,
                  float* __restrict__ C, int ldc, long strideC,
                  const float* __restrict__ bias, float alpha, int scale_q_cols)
{
    A += blockIdx.z * strideA;
    B += blockIdx.z * strideB;
    C += blockIdx.z * strideC;
    const int cCol = blockIdx.x, cRow = blockIdx.y;

    extern __shared__ unsigned dsmem[];
    unsigned* AsH = dsmem;               // [2][PLANE]
    unsigned* AsL = dsmem + 2 * PLANE;
    unsigned* BsH = dsmem + 4 * PLANE;
    unsigned* BsL = dsmem + 6 * PLANE;

    const int tid  = threadIdx.x;
    const int warp = tid >> 5, lane = tid & 31;
    const int warpM0 = (warp & 3) * 32, warpN0 = (warp >> 2) * 64;
    const int g = lane >> 2, tig = lane & 3;

    // Loads: 128 rows x 16 k. Each thread: row=tid>>1, k cols {c0, c0+8} (float4 each)
    const int aRow = tid >> 1, aCol = (tid & 1) * 4;
    const float* Aptr = A + (long)(cRow * BM + aRow) * lda + aCol;
    const float* Bptr = B + (long)(cCol * BN + aRow) * ldb + aCol;

    float acc[2][8][4];
    #pragma unroll
    for (int mt = 0; mt < 2; mt++)
        #pragma unroll
        for (int nt = 0; nt < 8; nt++)
            #pragma unroll
            for (int r = 0; r < 4; r++) acc[mt][nt][r] = 0.0f;

    float4 a0 = *reinterpret_cast<const float4*>(Aptr);
    float4 a1 = *reinterpret_cast<const float4*>(Aptr + 8);
    float4 b0 = *reinterpret_cast<const float4*>(Bptr);
    float4 b1 = *reinterpret_cast<const float4*>(Bptr + 8);
    store_kmajor4(AsH, AsL, aCol,     aRow, a0);
    store_kmajor4(AsH, AsL, aCol + 8, aRow, a1);
    store_kmajor4(BsH, BsL, aCol,     aRow, b0);
    store_kmajor4(BsH, BsL, aCol + 8, aRow, b1);
    __syncthreads();

    int buf = 0;
    for (int k0 = BK; k0 < K; k0 += BK) {
        Aptr += BK;
        Bptr += BK;
        a0 = *reinterpret_cast<const float4*>(Aptr);
        a1 = *reinterpret_cast<const float4*>(Aptr + 8);
        b0 = *reinterpret_cast<const float4*>(Bptr);
        b1 = *reinterpret_cast<const float4*>(Bptr + 8);

        const int so = buf * PLANE;
        mma_block(AsH + so,             AsL + so,             BsH + so,             BsL + so,             warpM0, warpN0, g, tig, acc);
        mma_block(AsH + so + 8 * PITCH, AsL + so + 8 * PITCH, BsH + so + 8 * PITCH, BsL + so + 8 * PITCH, warpM0, warpN0, g, tig, acc);

        const int nb = buf ^ 1, no = nb * PLANE;
        store_kmajor4(AsH + no, AsL + no, aCol,     aRow, a0);
        store_kmajor4(AsH + no, AsL + no, aCol + 8, aRow, a1);
        store_kmajor4(BsH + no, BsL + no, aCol,     aRow, b0);
        store_kmajor4(BsH + no, BsL + no, aCol + 8, aRow, b1);
        __syncthreads();
        buf = nb;
    }
    {
        const int so = buf * PLANE;
        mma_block(AsH + so,             AsL + so,             BsH + so,             BsL + so,             warpM0, warpN0, g, tig, acc);
        mma_block(AsH + so + 8 * PITCH, AsL + so + 8 * PITCH, BsH + so + 8 * PITCH, BsL + so + 8 * PITCH, warpM0, warpN0, g, tig, acc);
    }

    // Epilogue: C = s(n) * (acc + bias[n]); q-scaling folded for cols [0,DIM)
    #pragma unroll
    for (int mt = 0; mt < 2; mt++) {
        const int m0 = cRow * BM + warpM0 + mt * 16 + g;
        #pragma unroll
        for (int nt = 0; nt < 8; nt++) {
            const int n = cCol * BN + warpN0 + nt * 8 + 2 * tig;
            const float s = (scale_q_cols && n < DIM)
                          ? alpha * 0.04419417382415922f  // 512^-0.5
                          : alpha;
            float b0e = 0.0f, b1e = 0.0f;
            if (bias) { b0e = bias[n]; b1e = bias[n + 1]; }
            float2 o0, o1;
            o0.x = s * (acc[mt][nt][0] + b0e);
            o0.y = s * (acc[mt][nt][1] + b1e);
            o1.x = s * (acc[mt][nt][2] + b0e);
            o1.y = s * (acc[mt][nt][3] + b1e);
            *reinterpret_cast<float2*>(&C[(long)m0 * ldc + n]) = o0;
            *reinterpret_cast<float2*>(&C[(long)(m0 + 8) * ldc + n]) = o1;
        }
    }
}

// ---------------------------------------------------------------------------
// NN: C[m,n] = sum_k A[m,k] * B[k,n];  A: [M,K] rm (lda), B: [K,N] rm (ldb)
// K % 16 == 0.
// ---------------------------------------------------------------------------
__global__ __launch_bounds__(256, 2)
void gemm_nn_tf32(int M, int N, int K,
                  const float* __restrict__ A, int lda, long strideA,
                  const float* __restrict__ B, int ldb, long strideB,
                  float* __restrict__ C, int ldc, long strideC)
{
    A += blockIdx.z * strideA;
    B += blockIdx.z * strideB;
    C += blockIdx.z * strideC;
    const int cCol = blockIdx.x, cRow = blockIdx.y;

    extern __shared__ unsigned dsmem[];
    unsigned* AsH = dsmem;
    unsigned* AsL = dsmem + 2 * PLANE;
    unsigned* BsH = dsmem + 4 * PLANE;
    unsigned* BsL = dsmem + 6 * PLANE;

    const int tid  = threadIdx.x;
    const int warp = tid >> 5, lane = tid & 31;
    const int warpM0 = (warp & 3) * 32, warpN0 = (warp >> 2) * 64;
    const int g = lane >> 2, tig = lane & 3;

    const int aRow = tid >> 1, aCol = (tid & 1) * 4;
    const int bRow = tid >> 5, bCol = (tid & 31) * 4;   // B: k-rows {bRow, bRow+8} x 128 n

    const float* Aptr = A + (long)(cRow * BM + aRow) * lda + aCol;
    const float* Bptr = B + (long)bRow * ldb + cCol * BN + bCol;

    float acc[2][8][4];
    #pragma unroll
    for (int mt = 0; mt < 2; mt++)
        #pragma unroll
        for (int nt = 0; nt < 8; nt++)
            #pragma unroll
            for (int r = 0; r < 4; r++) acc[mt][nt][r] = 0.0f;

    float4 a0 = *reinterpret_cast<const float4*>(Aptr);
    float4 a1 = *reinterpret_cast<const float4*>(Aptr + 8);
    float4 b0 = *reinterpret_cast<const float4*>(Bptr);
    float4 b1 = *reinterpret_cast<const float4*>(Bptr + (long)8 * ldb);
    store_kmajor4(AsH, AsL, aCol,     aRow, a0);
    store_kmajor4(AsH, AsL, aCol + 8, aRow, a1);
    {
        unsigned h0,h1,h2,h3,l0,l1,l2,l3;
        split_tf32(b0.x, h0, l0); split_tf32(b0.y, h1, l1);
        split_tf32(b0.z, h2, l2); split_tf32(b0.w, h3, l3);
        *reinterpret_cast<uint4*>(&BsH[ bRow      * PITCH + bCol]) = make_uint4(h0, h1, h2, h3);
        *reinterpret_cast<uint4*>(&BsL[ bRow      * PITCH + bCol]) = make_uint4(l0, l1, l2, l3);
        split_tf32(b1.x, h0, l0); split_tf32(b1.y, h1, l1);
        split_tf32(b1.z, h2, l2); split_tf32(b1.w, h3, l3);
        *reinterpret_cast<uint4*>(&BsH[(bRow + 8) * PITCH + bCol]) = make_uint4(h0, h1, h2, h3);
        *reinterpret_cast<uint4*>(&BsL[(bRow + 8) * PITCH + bCol]) = make_uint4(l0, l1, l2, l3);
    }
    __syncthreads();

    int buf = 0;
    for (int k0 = BK; k0 < K; k0 += BK) {
        Aptr += BK;
        Bptr += (long)BK * ldb;
        a0 = *reinterpret_cast<const float4*>(Aptr);
        a1 = *reinterpret_cast<const float4*>(Aptr + 8);
        b0 = *reinterpret_cast<const float4*>(Bptr);
        b1 = *reinterpret_cast<const float4*>(Bptr + (long)8 * ldb);

        const int so = buf * PLANE;
        mma_block(AsH + so,             AsL + so,             BsH + so,             BsL + so,             warpM0, warpN0, g, tig, acc);
        mma_block(AsH + so + 8 * PITCH, AsL + so + 8 * PITCH, BsH + so + 8 * PITCH, BsL + so + 8 * PITCH, warpM0, warpN0, g, tig, acc);

        const int nb = buf ^ 1, no = nb * PLANE;
        store_kmajor4(AsH + no, AsL + no, aCol,     aRow, a0);
        store_kmajor4(AsH + no, AsL + no, aCol + 8, aRow, a1);
        unsigned h0,h1,h2,h3,l0,l1,l2,l3;
        split_tf32(b0.x, h0, l0); split_tf32(b0.y, h1, l1);
        split_tf32(b0.z, h2, l2); split_tf32(b0.w, h3, l3);
        *reinterpret_cast<uint4*>(&BsH[no +  bRow      * PITCH + bCol]) = make_uint4(h0, h1, h2, h3);
        *reinterpret_cast<uint4*>(&BsL[no +  bRow      * PITCH + bCol]) = make_uint4(l0, l1, l2, l3);
        split_tf32(b1.x, h0, l0); split_tf32(b1.y, h1, l1);
        split_tf32(b1.z, h2, l2); split_tf32(b1.w, h3, l3);
        *reinterpret_cast<uint4*>(&BsH[no + (bRow + 8) * PITCH + bCol]) = make_uint4(h0, h1, h2, h3);
        *reinterpret_cast<uint4*>(&BsL[no + (bRow + 8) * PITCH + bCol]) = make_uint4(l0, l1, l2, l3);
        __syncthreads();
        buf = nb;
    }
    {
        const int so = buf * PLANE;
        mma_block(AsH + so,             AsL + so,             BsH + so,             BsL + so,             warpM0, warpN0, g, tig, acc);
        mma_block(AsH + so + 8 * PITCH, AsL + so + 8 * PITCH, BsH + so + 8 * PITCH, BsL + so + 8 * PITCH, warpM0, warpN0, g, tig, acc);
    }

    #pragma unroll
    for (int mt = 0; mt < 2; mt++) {
        const int m0 = cRow * BM + warpM0 + mt * 16 + g;
        #pragma unroll
        for (int nt = 0; nt < 8; nt++) {
            const int n = cCol * BN + warpN0 + nt * 8 + 2 * tig;
            float2 o0, o1;
            o0.x = acc[mt][nt][0];
            o0.y = acc[mt][nt][1];
            o1.x = acc[mt][nt][2];
            o1.y = acc[mt][nt][3];
            *reinterpret_cast<float2*>(&C[(long)m0 * ldc + n]) = o0;
            *reinterpret_cast<float2*>(&C[(long)(m0 + 8) * ldc + n]) = o1;
        }
    }
}

// ---------------------------------------------------------------------------
// Row softmax over SEQ=2048 elements, in place. One block (256 thr) per row.
// ---------------------------------------------------------------------------
__global__ __launch_bounds__(256)
void softmax_rows(float* __restrict__ S)
{
    float* row = S + (long)blockIdx.x * SEQ;
    const int tid = threadIdx.x;
    const int lane = tid & 31;
    const int warp = tid >> 5;
    __shared__ float red[8];
    __shared__ float bcast;

    float4 v0 = reinterpret_cast<float4*>(row)[tid];
    float4 v1 = reinterpret_cast<float4*>(row)[tid + 256];

    float m = fmaxf(fmaxf(fmaxf(v0.x, v0.y), fmaxf(v0.z, v0.w)),
                    fmaxf(fmaxf(v1.x, v1.y), fmaxf(v1.z, v1.w)));
    #pragma unroll
    for (int o = 16; o > 0; o >>= 1)
        m = fmaxf(m, __shfl_xor_sync(0xffffffffu, m, o));
    if (lane == 0) red[warp] = m;
    __syncthreads();
    if (warp == 0) {
        float t = red[lane & 7];
        #pragma unroll
        for (int o = 4; o > 0; o >>= 1)
            t = fmaxf(t, __shfl_xor_sync(0xffffffffu, t, o));
        if (lane == 0) bcast = t;
    }
    __syncthreads();
    m = bcast;

    v0.x = __expf(v0.x - m); v0.y = __expf(v0.y - m);
    v0.z = __expf(v0.z - m); v0.w = __expf(v0.w - m);
    v1.x = __expf(v1.x - m); v1.y = __expf(v1.y - m);
    v1.z = __expf(v1.z - m); v1.w = __expf(v1.w - m);
    float s = (v0.x + v0.y + v0.z + v0.w) + (v1.x + v1.y + v1.z + v1.w);
    #pragma unroll
    for (int o = 16; o > 0; o >>= 1)
        s += __shfl_xor_sync(0xffffffffu, s, o);
    __syncthreads();
    if (lane == 0) red[warp] = s;
    __syncthreads();
    if (warp == 0) {
        float t = red[lane & 7];
        #pragma unroll
        for (int o = 4; o > 0; o >>= 1)
            t += __shfl_xor_sync(0xffffffffu, t, o);
        if (lane == 0) bcast = t;
    }
    __syncthreads();
    const float inv = 1.0f / bcast;

    v0.x *= inv; v0.y *= inv; v0.z *= inv; v0.w *= inv;
    v1.x *= inv; v1.y *= inv; v1.z *= inv; v1.w *= inv;
    reinterpret_cast<float4*>(row)[tid] = v0;
    reinterpret_cast<float4*>(row)[tid + 256] = v1;
}

// ---------------------------------------------------------------------------
// Launch
// ---------------------------------------------------------------------------
extern "C" void kernel_launch(void* const* d_in, const int* in_sizes, int n_in,
                              void* d_out, int out_size)
{
    const float* x      = (const float*)d_in[0];  // [4,2048,512]
    const float* qkv_w  = (const float*)d_in[1];  // [1536,512]
    const float* qkv_b  = (const float*)d_in[2];  // [1536]
    const float* out_w  = (const float*)d_in[3];  // [512,512]
    const float* out_b  = (const float*)d_in[4];  // [512]
    float* out = (float*)d_out;                   // [4,2048,512]

    float *qkv, *scores, *attn;
    cudaGetSymbolAddress((void**)&qkv, g_qkv);
    cudaGetSymbolAddress((void**)&scores, g_scores);
    cudaGetSymbolAddress((void**)&attn, g_attn);

    // Dynamic-smem opt-in (host-side attribute set; not stream-ordered,
    // graph-capture safe; deterministic/idempotent every call).
    cudaFuncSetAttribute(gemm_nt_tf32,
                         cudaFuncAttributeMaxDynamicSharedMemorySize, SMEM_BYTES);
    cudaFuncSetAttribute(gemm_nn_tf32,
                         cudaFuncAttributeMaxDynamicSharedMemorySize, SMEM_BYTES);

    const int M  = BATCH * SEQ;       // 8192
    const int D3 = 3 * DIM;           // 1536

    // 1) QKV projection (+bias); q columns [0,DIM) pre-scaled by 512^-0.5
    gemm_nt_tf32<<<dim3(D3 / BN, M / BM, 1), 256, SMEM_BYTES>>>(
        M, D3, DIM,
        x, DIM, 0L,
        qkv_w, DIM, 0L,
        qkv, D3, 0L,
        qkv_b, 1.0f, /*scale_q_cols=*/1);

    // 2) Scores: per batch, q_scaled @ k^T -> g_scores [b,2048,2048]
    gemm_nt_tf32<<<dim3(SEQ / BN, SEQ / BM, BATCH), 256, SMEM_BYTES>>>(
        SEQ, SEQ, DIM,
        qkv + 0,   D3, (long)SEQ * D3,     // q (already scaled)
        qkv + DIM, D3, (long)SEQ * D3,     // k
        scores, SEQ, (long)SEQ * SEQ,
        nullptr, 1.0f, 0);

    // 3) Softmax in place over last dim
    softmax_rows<<<BATCH * SEQ, 256>>>(scores);

    // 4) attn @ v -> g_attn [b,2048,512]
    gemm_nn_tf32<<<dim3(DIM / BN, SEQ / BM, BATCH), 256, SMEM_BYTES>>>(
        SEQ, DIM, SEQ,
        scores, SEQ, (long)SEQ * SEQ,
        qkv + 2 * DIM, D3, (long)SEQ * D3, // v
        attn, DIM, (long)SEQ * DIM);

    // 5) Output projection: [8192,512] @ [512,512]^T + bias -> d_out
    gemm_nt_tf32<<<dim3(DIM / BN, M / BM, 1), 256, SMEM_BYTES>>>(
        M, DIM, DIM,
        attn, DIM, 0L,
        out_w, DIM, 0L,
        out, DIM, 0L,
        out_b, 1.0f, 0);
}